// round 13
// baseline (speedup 1.0000x reference)
#include <cuda_runtime.h>
#include <cuda_bf16.h>
#include <math.h>
#include <float.h>

#define NN   768
#define DIMX 384
#define HH   12
#define PDD  128

static __device__ __constant__ float SCALAR_SCALE = 0.14433756729740643f; // (3*16)^-0.5
static __device__ __constant__ float POINT_SCALE  = 0.13608276348795434f; // (3*4*4.5)^-0.5
static __device__ __constant__ float PAIR_SCALE   = 0.5773502691896258f;  // 3^-0.5
#define EPSF 1e-8f

// ---- packed f32x2 helpers (sm_103a) ----
#define FMA_F32X2(d, a, b, c) \
    asm("fma.rn.f32x2 %0, %1, %2, %3;" : "=l"(d) : "l"(a), "l"(b), "l"(c))
#define PACK2(out, lo_u, hi_u) \
    asm("mov.b64 %0, {%1, %2};" : "=l"(out) : "r"(lo_u), "r"(hi_u))
#define UNPK2(lo_u, hi_u, in) \
    asm("mov.b64 {%0, %1}, %2;" : "=r"(lo_u), "=r"(hi_u) : "l"(in))

// ---- scratch ----
__device__ float g_qs[HH * NN * 16];
__device__ float g_qp[HH * NN * 12];
__device__ float g_kT[HH * 28 * NN];           // transposed k-features: [h][d(28)][j]
__device__ float g_v [HH * NN * 28];           // combined v_s(16) + v_p(12) per (h,j)
__device__ float g_rp[3][(size_t)NN * 1536];   // r_pair j-slice partials
__device__ float g_results[(size_t)NN * 1920];
__device__ float g_opart[6][(size_t)NN * DIMX];

// ============ kernel 1: all projections, 8 residues/block, f32x2 row pairs ============
__global__ void __launch_bounds__(1008)
k_proj(const float* __restrict__ x,
       const float* __restrict__ Wqs, const float* __restrict__ Wks,
       const float* __restrict__ Wvs,
       const float* __restrict__ Wqp, const float* __restrict__ Wkp,
       const float* __restrict__ Wvp,
       const float* __restrict__ rot, const float* __restrict__ trs) {
    __shared__ unsigned long long spack[DIMX][4];
    __shared__ float sloc[8][432];
    const int i0 = blockIdx.x * 8, t = threadIdx.x;

    for (int k = t; k < 4 * DIMX; k += 1008) {
        const int rp = k / DIMX, c = k % DIMX;
        unsigned long long v;
        PACK2(v, __float_as_uint(x[(i0 + 2 * rp) * DIMX + c]),
                 __float_as_uint(x[(i0 + 2 * rp + 1) * DIMX + c]));
        spack[c][rp] = v;
    }
    __syncthreads();

    unsigned long long acc[4] = {0ull, 0ull, 0ull, 0ull};
    if (t < 576) {
        const float* W; int cc;
        if (t < 192)      { W = Wqs; cc = t; }
        else if (t < 384) { W = Wks; cc = t - 192; }
        else              { W = Wvs; cc = t - 384; }
#pragma unroll 4
        for (int c = 0; c < DIMX; c++) {
            const float w = __ldg(&W[c * 192 + cc]);
            unsigned long long wp; PACK2(wp, __float_as_uint(w), __float_as_uint(w));
#pragma unroll
            for (int q = 0; q < 4; q++) FMA_F32X2(acc[q], spack[c][q], wp, acc[q]);
        }
        const int h = (t % 192) >> 4, d = t & 15;
#pragma unroll
        for (int q = 0; q < 4; q++) {
            unsigned lo, hi; UNPK2(lo, hi, acc[q]);
            if (t < 192) {
                g_qs[((h * NN) + i0 + 2 * q) * 16 + d]     = __uint_as_float(lo);
                g_qs[((h * NN) + i0 + 2 * q + 1) * 16 + d] = __uint_as_float(hi);
            } else if (t < 384) {
                g_kT[(h * 28 + d) * NN + i0 + 2 * q]     = __uint_as_float(lo);
                g_kT[(h * 28 + d) * NN + i0 + 2 * q + 1] = __uint_as_float(hi);
            } else {
                g_v[((h * NN) + i0 + 2 * q) * 28 + d]     = __uint_as_float(lo);
                g_v[((h * NN) + i0 + 2 * q + 1) * 28 + d] = __uint_as_float(hi);
            }
        }
    } else {
        const int cc = t - 576, m = cc / 144, ccl = cc % 144;
        const float* W = (m == 0) ? Wqp : (m == 1) ? Wkp : Wvp;
#pragma unroll 4
        for (int c = 0; c < DIMX; c++) {
            const float w = __ldg(&W[c * 144 + ccl]);
            unsigned long long wp; PACK2(wp, __float_as_uint(w), __float_as_uint(w));
#pragma unroll
            for (int q = 0; q < 4; q++) FMA_F32X2(acc[q], spack[c][q], wp, acc[q]);
        }
#pragma unroll
        for (int q = 0; q < 4; q++) {
            unsigned lo, hi; UNPK2(lo, hi, acc[q]);
            sloc[2 * q][cc]     = __uint_as_float(lo);
            sloc[2 * q + 1][cc] = __uint_as_float(hi);
        }
    }
    __syncthreads();
    if (t >= 576) {
        const int cc = t - 576, m = cc / 144, ccl = cc % 144;
        const int rr = ccl % 3, hp = ccl / 3, h = hp >> 2, p = hp & 3;
        const int base = m * 144 + hp * 3;
#pragma unroll
        for (int r = 0; r < 8; r++) {
            const float* R = rot + (i0 + r) * 9;
            const float v = sloc[r][base + 0] * R[rr * 3 + 0]
                          + sloc[r][base + 1] * R[rr * 3 + 1]
                          + sloc[r][base + 2] * R[rr * 3 + 2]
                          + trs[(i0 + r) * 3 + rr];
            if (m == 0)      g_qp[((h * NN) + i0 + r) * 12 + p * 3 + rr] = v;
            else if (m == 1) g_kT[(h * 28 + 16 + p * 3 + rr) * NN + i0 + r] = v;
            else             g_v [((h * NN) + i0 + r) * 28 + 16 + p * 3 + rr] = v;
        }
    }
}

// ============ kernel 2: fused qk + bias + softmax + r_pair + r_scalar/point ============
// 768 threads = 24 warps; 2 query residues per block; 2 blocks/SM.
// smem float layout (21228 floats = 84912 B):
//   sl    [0, 18432)        24 rows x 768 logits/attn
//   sW    [18432, 19968)    W_pair^T as f4: [12 h][32 d4]
//   sq    [19968, 20640)    24 rows x 28 q-features
//   sbp   [20640, 20652)    b_pair
//   sp2   [20652, 20940)    [h][r][12]
//   sro   [20940, 21228)    [h][r][12]
__global__ void __launch_bounds__(768, 2)
k_fused(const float* __restrict__ pair, const float* __restrict__ Wp,
        const float* __restrict__ bp,
        const float* __restrict__ rot, const float* __restrict__ trs,
        const float* __restrict__ pwts) {
    extern __shared__ float sdyn[];
    float* sl   = sdyn;
    float* sW   = sdyn + 18432;
    float* sq   = sdyn + 19968;
    float* sbp  = sdyn + 20640;
    float* sp2  = sdyn + 20652;
    float* sro  = sdyn + 20940;
    const int i0 = blockIdx.x * 2, t = threadIdx.x, w = t >> 5, lane = t & 31;

    // ---- stage W_pair^T f4, q features, b_pair ----
    if (t < 384) {
        const int h = t >> 5, d4 = t & 31;
        const float4 v = make_float4(__ldg(&Wp[(d4 * 4 + 0) * HH + h]),
                                     __ldg(&Wp[(d4 * 4 + 1) * HH + h]),
                                     __ldg(&Wp[(d4 * 4 + 2) * HH + h]),
                                     __ldg(&Wp[(d4 * 4 + 3) * HH + h]));
        *reinterpret_cast<float4*>(&sW[(h * 32 + d4) * 4]) = v;
    }
    if (t < 672) {
        const int row = t / 28, dd = t % 28, r = row / 12, h = row % 12;
        sq[row * 28 + dd] = (dd < 16) ? g_qs[(h * NN + i0 + r) * 16 + dd]
                                      : g_qp[(h * NN + i0 + r) * 12 + dd - 16];
    }
    if (t < 12) sbp[t] = __ldg(&bp[t]);
    __syncthreads();

    // ---- phase 0: qk logits via transposed k (coalesced LDG.32) ----
    {
        const int row = w, h = w % 12;
        const float coef = 0.5f * POINT_SCALE * log1pf(expf(__ldg(&pwts[h])));
        const float* kT = g_kT + (size_t)h * 28 * NN;
        const float* sqr = sq + row * 28;
        for (int j = lane; j < NN; j += 32) {
            float dot = 0.f, dist = 0.f;
#pragma unroll
            for (int d = 0; d < 16; d++) dot = fmaf(sqr[d], __ldg(&kT[d * NN + j]), dot);
#pragma unroll
            for (int d = 0; d < 12; d++) {
                const float df = sqr[16 + d] - __ldg(&kT[(16 + d) * NN + j]);
                dist = fmaf(df, df, dist);
            }
            sl[row * NN + j] = fmaf(dot, SCALAR_SCALE, -coef * dist);
        }
    }
    __syncthreads();

    // ---- phase 1: pair-bias GEMM; 8 j-rows x 4 d-lanes per warp group (nL=8);
    //      h processed in two 6-h passes to keep regs <= 42 (2nd pass L1-hits) ----
    {
        const int jr = lane >> 2, dd = lane & 3;
#pragma unroll
        for (int gi = 0; gi < 8; gi++) {
            const int g = w + gi * 24;            // 0..191
            const int r = g / 96, jb = (g % 96) * 8 + jr;
            const ulonglong2* prow = reinterpret_cast<const ulonglong2*>(
                pair + ((size_t)(i0 + r) * NN + jb) * PDD);
            float b[12];
#pragma unroll
            for (int hp = 0; hp < 2; hp++) {
                unsigned long long acc[6];
#pragma unroll
                for (int hh = 0; hh < 6; hh++) acc[hh] = 0ull;
#pragma unroll
                for (int q = 0; q < 8; q++) {
                    const ulonglong2 p = __ldg(&prow[q * 4 + dd]);
#pragma unroll
                    for (int hh = 0; hh < 6; hh++) {
                        const ulonglong2 wv = *reinterpret_cast<const ulonglong2*>(
                            &sW[((hp * 6 + hh) * 32 + q * 4 + dd) * 4]);
                        FMA_F32X2(acc[hh], p.x, wv.x, acc[hh]);
                        FMA_F32X2(acc[hh], p.y, wv.y, acc[hh]);
                    }
                }
#pragma unroll
                for (int hh = 0; hh < 6; hh++) {
                    unsigned lo, hi; UNPK2(lo, hi, acc[hh]);
                    b[hp * 6 + hh] = __uint_as_float(lo) + __uint_as_float(hi);
                }
            }
#pragma unroll
            for (int h = 0; h < 12; h++) {
                b[h] += __shfl_xor_sync(0xffffffffu, b[h], 1);
                b[h] += __shfl_xor_sync(0xffffffffu, b[h], 2);
            }
#pragma unroll
            for (int u = 0; u < 3; u++) {
                const int h = dd * 3 + u;
                float* p = &sl[(r * 12 + h) * NN + jb];
                *p = fmaf(b[h] + sbp[h], PAIR_SCALE, *p);
            }
        }
    }
    __syncthreads();

    // ---- phase 2: softmax per row (24 rows = 24 warps) ----
    {
        float* rl = sl + w * NN;
        float m = -FLT_MAX;
        for (int j = lane; j < NN; j += 32) m = fmaxf(m, rl[j]);
#pragma unroll
        for (int off = 16; off; off >>= 1) m = fmaxf(m, __shfl_xor_sync(0xffffffffu, m, off));
        float s = 0.f;
        for (int j = lane; j < NN; j += 32) { const float e = __expf(rl[j] - m); rl[j] = e; s += e; }
#pragma unroll
        for (int off = 16; off; off >>= 1) s += __shfl_xor_sync(0xffffffffu, s, off);
        const float inv = 1.f / s;
        for (int j = lane; j < NN; j += 32) rl[j] *= inv;
    }
    __syncthreads();

    // ---- phase 3: 12 pair-warps (r x h-half x j-third) write partials to gmem;
    //              12 v-warps do r_scalar/r_point concurrently ----
    if (w < 12) {
        const int r = w & 1, hg = (w >> 1) & 1, slice = w >> 2;   // slice 0..2
        const int j0 = slice * 256, h0 = hg * 6;
        unsigned long long acc[6][2];
#pragma unroll
        for (int hh = 0; hh < 6; hh++) { acc[hh][0] = 0ull; acc[hh][1] = 0ull; }
        const float4* pbase = reinterpret_cast<const float4*>(
            pair + (size_t)(i0 + r) * NN * PDD) + lane;
        const float* arow = sl + (r * 12 + h0) * NN + j0;
#pragma unroll 2
        for (int j = 0; j < 256; j++) {
            const float4 p = __ldg(pbase + (size_t)(j0 + j) * 32);
            unsigned long long p01, p23;
            PACK2(p01, __float_as_uint(p.x), __float_as_uint(p.y));
            PACK2(p23, __float_as_uint(p.z), __float_as_uint(p.w));
#pragma unroll
            for (int hh = 0; hh < 6; hh++) {
                const float a = arow[hh * NN + j];
                unsigned long long aa;
                PACK2(aa, __float_as_uint(a), __float_as_uint(a));
                FMA_F32X2(acc[hh][0], p01, aa, acc[hh][0]);
                FMA_F32X2(acc[hh][1], p23, aa, acc[hh][1]);
            }
        }
        float* rp = g_rp[slice] + (size_t)(i0 + r) * 1536;
#pragma unroll
        for (int hh = 0; hh < 6; hh++) {
            unsigned a0, a1, b0, b1;
            UNPK2(a0, a1, acc[hh][0]); UNPK2(b0, b1, acc[hh][1]);
            *reinterpret_cast<float4*>(&rp[(h0 + hh) * 128 + lane * 4]) =
                make_float4(__uint_as_float(a0), __uint_as_float(a1),
                            __uint_as_float(b0), __uint_as_float(b1));
        }
    } else {
        const int h = w - 12;
        float a0 = 0.f, a1 = 0.f;
        if (lane < 28) {
            const float* vrow = g_v + (size_t)h * NN * 28 + lane;
            const float* s0 = sl + h * NN;
            const float* s1 = sl + (12 + h) * NN;
#pragma unroll 4
            for (int j = 0; j < NN; j++) {
                const float v = __ldg(vrow + (size_t)j * 28);
                a0 = fmaf(s0[j], v, a0);
                a1 = fmaf(s1[j], v, a1);
            }
            if (lane < 16) {
                g_results[(size_t)(i0 + 0) * 1920 + h * 16 + lane] = a0;
                g_results[(size_t)(i0 + 1) * 1920 + h * 16 + lane] = a1;
            } else {
                sp2[(h * 2 + 0) * 12 + lane - 16] = a0;
                sp2[(h * 2 + 1) * 12 + lane - 16] = a1;
            }
        }
        __syncwarp();
        if (lane < 24) {
            const int r = lane / 12, u = lane % 12, p = u / 3, rr = u % 3;
            const int i = i0 + r;
            const float* R = rot + i * 9;
            const float* T = trs + i * 3;
            const float* s = &sp2[(h * 2 + r) * 12 + p * 3];
            const float v = (s[0] - T[0]) * R[0 * 3 + rr]
                          + (s[1] - T[1]) * R[1 * 3 + rr]
                          + (s[2] - T[2]) * R[2 * 3 + rr];
            sro[(h * 2 + r) * 12 + u] = v;
            g_results[(size_t)i * 1920 + 192 + (h * 4 + p) * 3 + rr] = v;
        }
        __syncwarp();
        if (lane < 8) {
            const int r = lane / 4, p = lane % 4, i = i0 + r;
            const float* s = &sro[(h * 2 + r) * 12 + p * 3];
            g_results[(size_t)i * 1920 + 336 + h * 4 + p] =
                sqrtf(s[0] * s[0] + s[1] * s[1] + s[2] * s[2] + EPSF);
        }
    }
}

// ============ kernel 2b: combine r_pair j-slice partials ============
__global__ void __launch_bounds__(384) k_comb() {
    const int i = blockIdx.x, t = threadIdx.x;
    const float4 a = *reinterpret_cast<const float4*>(&g_rp[0][(size_t)i * 1536 + t * 4]);
    const float4 b = *reinterpret_cast<const float4*>(&g_rp[1][(size_t)i * 1536 + t * 4]);
    const float4 c = *reinterpret_cast<const float4*>(&g_rp[2][(size_t)i * 1536 + t * 4]);
    *reinterpret_cast<float4*>(&g_results[(size_t)i * 1920 + 384 + t * 4]) =
        make_float4(a.x + b.x + c.x, a.y + b.y + c.y,
                    a.z + b.z + c.z, a.w + b.w + c.w);
}

// ============ kernel 3: output GEMM partials (grid 48 x 6) ============
__global__ void __launch_bounds__(384) k_out(const float* __restrict__ Wo) {
    __shared__ float2 sr2[512];
    const int i0 = blockIdx.x * 16, cbase = blockIdx.y * 320, o = threadIdx.x;
    unsigned long long acc[8];
#pragma unroll
    for (int q = 0; q < 8; q++) acc[q] = 0ull;

    for (int c0 = cbase; c0 < cbase + 320; c0 += 64) {
        __syncthreads();
        for (int k = o; k < 512; k += 384) {
            const int q = k >> 6, cc = k & 63;
            const float f0 = g_results[(size_t)(i0 + 2 * q) * 1920 + c0 + cc];
            const float f1 = g_results[(size_t)(i0 + 2 * q + 1) * 1920 + c0 + cc];
            sr2[k] = make_float2(f0, f1);
        }
        __syncthreads();
#pragma unroll 8
        for (int cc = 0; cc < 64; cc++) {
            const float wv = __ldg(&Wo[(size_t)(c0 + cc) * DIMX + o]);
            unsigned long long ww;
            PACK2(ww, __float_as_uint(wv), __float_as_uint(wv));
#pragma unroll
            for (int q = 0; q < 8; q++) {
                const unsigned long long s =
                    *reinterpret_cast<const unsigned long long*>(&sr2[(q << 6) + cc]);
                FMA_F32X2(acc[q], s, ww, acc[q]);
            }
        }
    }
    float* op = g_opart[blockIdx.y];
#pragma unroll
    for (int q = 0; q < 8; q++) {
        unsigned lo, hi; UNPK2(lo, hi, acc[q]);
        op[(size_t)(i0 + 2 * q) * DIMX + o]     = __uint_as_float(lo);
        op[(size_t)(i0 + 2 * q + 1) * DIMX + o] = __uint_as_float(hi);
    }
}

// ============ kernel 4: reduce partials + bias ============
__global__ void k_out_red(const float* __restrict__ bo, float* __restrict__ out) {
    const int i = blockIdx.x, o = threadIdx.x;
    const size_t idx = (size_t)i * DIMX + o;
    out[idx] = g_opart[0][idx] + g_opart[1][idx] + g_opart[2][idx]
             + g_opart[3][idx] + g_opart[4][idx] + g_opart[5][idx] + bo[o];
}

// ============ launch ============
extern "C" void kernel_launch(void* const* d_in, const int* in_sizes, int n_in,
                              void* d_out, int out_size) {
    const float* x    = (const float*)d_in[0];
    const float* pair = (const float*)d_in[1];
    const float* rot  = (const float*)d_in[2];
    const float* trs  = (const float*)d_in[3];
    // d_in[4] = mask (all true) -> no-op
    const float* Wq_s = (const float*)d_in[5];
    const float* Wk_s = (const float*)d_in[6];
    const float* Wv_s = (const float*)d_in[7];
    const float* Wq_p = (const float*)d_in[8];
    const float* Wk_p = (const float*)d_in[9];
    const float* Wv_p = (const float*)d_in[10];
    const float* Wpr  = (const float*)d_in[11];
    const float* bpr  = (const float*)d_in[12];
    const float* pwts = (const float*)d_in[13];
    const float* Wout = (const float*)d_in[14];
    const float* bout = (const float*)d_in[15];
    float* out = (float*)d_out;

    static bool attr_done = false;
    if (!attr_done) {
        cudaFuncSetAttribute(k_fused, cudaFuncAttributeMaxDynamicSharedMemorySize, 84912);
        attr_done = true;
    }

    k_proj<<<NN / 8, 1008>>>(x, Wq_s, Wk_s, Wv_s, Wq_p, Wk_p, Wv_p, rot, trs);
    k_fused<<<NN / 2, 768, 84912>>>(pair, Wpr, bpr, rot, trs, pwts);
    k_comb<<<NN, 384>>>();
    k_out<<<dim3(NN / 16, 6), 384>>>(Wout);
    k_out_red<<<NN, DIMX>>>(bout, out);
}

// round 14
// speedup vs baseline: 1.1703x; 1.1703x over previous
#include <cuda_runtime.h>
#include <cuda_bf16.h>
#include <math.h>
#include <float.h>

#define NN   768
#define DIMX 384
#define HH   12
#define PDD  128

static __device__ __constant__ float SCALAR_SCALE = 0.14433756729740643f; // (3*16)^-0.5
static __device__ __constant__ float POINT_SCALE  = 0.13608276348795434f; // (3*4*4.5)^-0.5
static __device__ __constant__ float PAIR_SCALE   = 0.5773502691896258f;  // 3^-0.5
#define EPSF 1e-8f

// ---- packed f32x2 helpers (sm_103a) ----
#define FMA_F32X2(d, a, b, c) \
    asm("fma.rn.f32x2 %0, %1, %2, %3;" : "=l"(d) : "l"(a), "l"(b), "l"(c))
#define PACK2(out, lo_u, hi_u) \
    asm("mov.b64 %0, {%1, %2};" : "=l"(out) : "r"(lo_u), "r"(hi_u))
#define UNPK2(lo_u, hi_u, in) \
    asm("mov.b64 {%0, %1}, %2;" : "=r"(lo_u), "=r"(hi_u) : "l"(in))

// ---- scratch ----
__device__ float g_qs[HH * NN * 16];
__device__ float g_qp[HH * NN * 12];
__device__ float g_kT[HH * 28 * NN];           // transposed k-features: [h][d(28)][j]
__device__ float g_v [HH * NN * 28];           // combined v_s(16) + v_p(12) per (h,j)
__device__ float g_rp[3][(size_t)NN * 1536];   // r_pair j-slice partials
__device__ float g_results[(size_t)NN * 1920];
__device__ float g_opart[6][(size_t)NN * DIMX];

// ============ kernel 1: all projections, 8 residues/block, f32x2 row pairs ============
__global__ void __launch_bounds__(1008)
k_proj(const float* __restrict__ x,
       const float* __restrict__ Wqs, const float* __restrict__ Wks,
       const float* __restrict__ Wvs,
       const float* __restrict__ Wqp, const float* __restrict__ Wkp,
       const float* __restrict__ Wvp,
       const float* __restrict__ rot, const float* __restrict__ trs) {
    __shared__ unsigned long long spack[DIMX][4];
    __shared__ float sloc[8][432];
    const int i0 = blockIdx.x * 8, t = threadIdx.x;

    for (int k = t; k < 4 * DIMX; k += 1008) {
        const int rp = k / DIMX, c = k % DIMX;
        unsigned long long v;
        PACK2(v, __float_as_uint(x[(i0 + 2 * rp) * DIMX + c]),
                 __float_as_uint(x[(i0 + 2 * rp + 1) * DIMX + c]));
        spack[c][rp] = v;
    }
    __syncthreads();

    unsigned long long acc[4] = {0ull, 0ull, 0ull, 0ull};
    if (t < 576) {
        const float* W; int cc;
        if (t < 192)      { W = Wqs; cc = t; }
        else if (t < 384) { W = Wks; cc = t - 192; }
        else              { W = Wvs; cc = t - 384; }
#pragma unroll 4
        for (int c = 0; c < DIMX; c++) {
            const float w = __ldg(&W[c * 192 + cc]);
            unsigned long long wp; PACK2(wp, __float_as_uint(w), __float_as_uint(w));
#pragma unroll
            for (int q = 0; q < 4; q++) FMA_F32X2(acc[q], spack[c][q], wp, acc[q]);
        }
        const int h = (t % 192) >> 4, d = t & 15;
#pragma unroll
        for (int q = 0; q < 4; q++) {
            unsigned lo, hi; UNPK2(lo, hi, acc[q]);
            if (t < 192) {
                g_qs[((h * NN) + i0 + 2 * q) * 16 + d]     = __uint_as_float(lo);
                g_qs[((h * NN) + i0 + 2 * q + 1) * 16 + d] = __uint_as_float(hi);
            } else if (t < 384) {
                g_kT[(h * 28 + d) * NN + i0 + 2 * q]     = __uint_as_float(lo);
                g_kT[(h * 28 + d) * NN + i0 + 2 * q + 1] = __uint_as_float(hi);
            } else {
                g_v[((h * NN) + i0 + 2 * q) * 28 + d]     = __uint_as_float(lo);
                g_v[((h * NN) + i0 + 2 * q + 1) * 28 + d] = __uint_as_float(hi);
            }
        }
    } else {
        const int cc = t - 576, m = cc / 144, ccl = cc % 144;
        const float* W = (m == 0) ? Wqp : (m == 1) ? Wkp : Wvp;
#pragma unroll 4
        for (int c = 0; c < DIMX; c++) {
            const float w = __ldg(&W[c * 144 + ccl]);
            unsigned long long wp; PACK2(wp, __float_as_uint(w), __float_as_uint(w));
#pragma unroll
            for (int q = 0; q < 4; q++) FMA_F32X2(acc[q], spack[c][q], wp, acc[q]);
        }
#pragma unroll
        for (int q = 0; q < 4; q++) {
            unsigned lo, hi; UNPK2(lo, hi, acc[q]);
            sloc[2 * q][cc]     = __uint_as_float(lo);
            sloc[2 * q + 1][cc] = __uint_as_float(hi);
        }
    }
    __syncthreads();
    if (t >= 576) {
        const int cc = t - 576, m = cc / 144, ccl = cc % 144;
        const int rr = ccl % 3, hp = ccl / 3, h = hp >> 2, p = hp & 3;
        const int base = m * 144 + hp * 3;
#pragma unroll
        for (int r = 0; r < 8; r++) {
            const float* R = rot + (i0 + r) * 9;
            const float v = sloc[r][base + 0] * R[rr * 3 + 0]
                          + sloc[r][base + 1] * R[rr * 3 + 1]
                          + sloc[r][base + 2] * R[rr * 3 + 2]
                          + trs[(i0 + r) * 3 + rr];
            if (m == 0)      g_qp[((h * NN) + i0 + r) * 12 + p * 3 + rr] = v;
            else if (m == 1) g_kT[(h * 28 + 16 + p * 3 + rr) * NN + i0 + r] = v;
            else             g_v [((h * NN) + i0 + r) * 28 + 16 + p * 3 + rr] = v;
        }
    }
}

// ============ kernel 2: fused qk + bias + softmax + r_pair + r_scalar/point ============
// 512 threads = 16 warps; 2 query residues per block; 2 blocks/SM (85KB smem, <=64 regs).
// smem float layout (21228 floats = 84912 B):
//   sl    [0, 18432)        24 rows x 768 logits/attn
//   sW    [18432, 19968)    W_pair^T as f4: [12 h][32 d4]
//   sq    [19968, 20640)    24 rows x 28 q-features
//   sbp   [20640, 20652)    b_pair
//   sp2   [20652, 20940)    [h][r][12]
//   sro   [20940, 21228)    [h][r][12]
__global__ void __launch_bounds__(512, 2)
k_fused(const float* __restrict__ pair, const float* __restrict__ Wp,
        const float* __restrict__ bp,
        const float* __restrict__ rot, const float* __restrict__ trs,
        const float* __restrict__ pwts) {
    extern __shared__ float sdyn[];
    float* sl   = sdyn;
    float* sW   = sdyn + 18432;
    float* sq   = sdyn + 19968;
    float* sbp  = sdyn + 20640;
    float* sp2  = sdyn + 20652;
    float* sro  = sdyn + 20940;
    const int i0 = blockIdx.x * 2, t = threadIdx.x, w = t >> 5, lane = t & 31;

    // ---- stage W_pair^T f4, q features, b_pair ----
    if (t < 384) {
        const int h = t >> 5, d4 = t & 31;
        const float4 v = make_float4(__ldg(&Wp[(d4 * 4 + 0) * HH + h]),
                                     __ldg(&Wp[(d4 * 4 + 1) * HH + h]),
                                     __ldg(&Wp[(d4 * 4 + 2) * HH + h]),
                                     __ldg(&Wp[(d4 * 4 + 3) * HH + h]));
        *reinterpret_cast<float4*>(&sW[(h * 32 + d4) * 4]) = v;
    }
    for (int k = t; k < 672; k += 512) {
        const int row = k / 28, dd = k % 28, r = row / 12, h = row % 12;
        sq[row * 28 + dd] = (dd < 16) ? g_qs[(h * NN + i0 + r) * 16 + dd]
                                      : g_qp[(h * NN + i0 + r) * 12 + dd - 16];
    }
    if (t < 12) sbp[t] = __ldg(&bp[t]);
    __syncthreads();

    // ---- phase 0: qk logits via transposed k (coalesced LDG.32); rows looped over warps ----
    for (int row = w; row < 24; row += 16) {
        const int h = row % 12;
        const float coef = 0.5f * POINT_SCALE * log1pf(expf(__ldg(&pwts[h])));
        const float* kT = g_kT + (size_t)h * 28 * NN;
        const float* sqr = sq + row * 28;
        for (int j = lane; j < NN; j += 32) {
            float dot = 0.f, dist = 0.f;
#pragma unroll
            for (int d = 0; d < 16; d++) dot = fmaf(sqr[d], __ldg(&kT[d * NN + j]), dot);
#pragma unroll
            for (int d = 0; d < 12; d++) {
                const float df = sqr[16 + d] - __ldg(&kT[(16 + d) * NN + j]);
                dist = fmaf(df, df, dist);
            }
            sl[row * NN + j] = fmaf(dot, SCALAR_SCALE, -coef * dist);
        }
    }
    __syncthreads();

    // ---- phase 1: pair-bias GEMM; 8 j-rows x 4 d-lanes per warp group (nL=8);
    //      single 12-h pass (acc 24 regs) ----
    {
        const int jr = lane >> 2, dd = lane & 3;
#pragma unroll
        for (int gi = 0; gi < 12; gi++) {
            const int g = w + gi * 16;            // 0..191
            const int r = g / 96, jb = (g % 96) * 8 + jr;
            const ulonglong2* prow = reinterpret_cast<const ulonglong2*>(
                pair + ((size_t)(i0 + r) * NN + jb) * PDD);
            unsigned long long acc[12];
#pragma unroll
            for (int h = 0; h < 12; h++) acc[h] = 0ull;
#pragma unroll
            for (int q = 0; q < 8; q++) {
                const ulonglong2 p = __ldg(&prow[q * 4 + dd]);
#pragma unroll
                for (int h = 0; h < 12; h++) {
                    const ulonglong2 wv = *reinterpret_cast<const ulonglong2*>(
                        &sW[(h * 32 + q * 4 + dd) * 4]);
                    FMA_F32X2(acc[h], p.x, wv.x, acc[h]);
                    FMA_F32X2(acc[h], p.y, wv.y, acc[h]);
                }
            }
            float b[12];
#pragma unroll
            for (int h = 0; h < 12; h++) {
                unsigned lo, hi; UNPK2(lo, hi, acc[h]);
                b[h] = __uint_as_float(lo) + __uint_as_float(hi);
                b[h] += __shfl_xor_sync(0xffffffffu, b[h], 1);
                b[h] += __shfl_xor_sync(0xffffffffu, b[h], 2);
            }
#pragma unroll
            for (int u = 0; u < 3; u++) {
                const int h = dd * 3 + u;
                float* p = &sl[(r * 12 + h) * NN + jb];
                *p = fmaf(b[h] + sbp[h], PAIR_SCALE, *p);
            }
        }
    }
    __syncthreads();

    // ---- phase 2: softmax per row; rows looped over warps ----
    for (int row = w; row < 24; row += 16) {
        float* rl = sl + row * NN;
        float m = -FLT_MAX;
        for (int j = lane; j < NN; j += 32) m = fmaxf(m, rl[j]);
#pragma unroll
        for (int off = 16; off; off >>= 1) m = fmaxf(m, __shfl_xor_sync(0xffffffffu, m, off));
        float s = 0.f;
        for (int j = lane; j < NN; j += 32) { const float e = __expf(rl[j] - m); rl[j] = e; s += e; }
#pragma unroll
        for (int off = 16; off; off >>= 1) s += __shfl_xor_sync(0xffffffffu, s, off);
        const float inv = 1.f / s;
        for (int j = lane; j < NN; j += 32) rl[j] *= inv;
    }
    __syncthreads();

    // ---- phase 3: 24 roles over 16 warps.
    //  roles 0..11 : r_pair partial (r x h-half x j-third) -> g_rp
    //  roles 12..23: r_scalar/r_point for head (role-12) ----
    for (int role = w; role < 24; role += 16) {
        if (role < 12) {
            const int r = role & 1, hg = (role >> 1) & 1, slice = role >> 2;   // 0..2
            const int j0 = slice * 256, h0 = hg * 6;
            unsigned long long acc[6][2];
#pragma unroll
            for (int hh = 0; hh < 6; hh++) { acc[hh][0] = 0ull; acc[hh][1] = 0ull; }
            const float4* pbase = reinterpret_cast<const float4*>(
                pair + (size_t)(i0 + r) * NN * PDD) + lane;
            const float* arow = sl + (r * 12 + h0) * NN + j0;
#pragma unroll 2
            for (int j = 0; j < 256; j++) {
                const float4 p = __ldg(pbase + (size_t)(j0 + j) * 32);
                unsigned long long p01, p23;
                PACK2(p01, __float_as_uint(p.x), __float_as_uint(p.y));
                PACK2(p23, __float_as_uint(p.z), __float_as_uint(p.w));
#pragma unroll
                for (int hh = 0; hh < 6; hh++) {
                    const float a = arow[hh * NN + j];
                    unsigned long long aa;
                    PACK2(aa, __float_as_uint(a), __float_as_uint(a));
                    FMA_F32X2(acc[hh][0], p01, aa, acc[hh][0]);
                    FMA_F32X2(acc[hh][1], p23, aa, acc[hh][1]);
                }
            }
            float* rp = g_rp[slice] + (size_t)(i0 + r) * 1536;
#pragma unroll
            for (int hh = 0; hh < 6; hh++) {
                unsigned a0, a1, b0, b1;
                UNPK2(a0, a1, acc[hh][0]); UNPK2(b0, b1, acc[hh][1]);
                *reinterpret_cast<float4*>(&rp[(h0 + hh) * 128 + lane * 4]) =
                    make_float4(__uint_as_float(a0), __uint_as_float(a1),
                                __uint_as_float(b0), __uint_as_float(b1));
            }
        } else {
            const int h = role - 12;
            float a0 = 0.f, a1 = 0.f;
            if (lane < 28) {
                const float* vrow = g_v + (size_t)h * NN * 28 + lane;
                const float* s0 = sl + h * NN;
                const float* s1 = sl + (12 + h) * NN;
#pragma unroll 4
                for (int j = 0; j < NN; j++) {
                    const float v = __ldg(vrow + (size_t)j * 28);
                    a0 = fmaf(s0[j], v, a0);
                    a1 = fmaf(s1[j], v, a1);
                }
                if (lane < 16) {
                    g_results[(size_t)(i0 + 0) * 1920 + h * 16 + lane] = a0;
                    g_results[(size_t)(i0 + 1) * 1920 + h * 16 + lane] = a1;
                } else {
                    sp2[(h * 2 + 0) * 12 + lane - 16] = a0;
                    sp2[(h * 2 + 1) * 12 + lane - 16] = a1;
                }
            }
            __syncwarp();
            if (lane < 24) {
                const int r = lane / 12, u = lane % 12, p = u / 3, rr = u % 3;
                const int i = i0 + r;
                const float* R = rot + i * 9;
                const float* T = trs + i * 3;
                const float* s = &sp2[(h * 2 + r) * 12 + p * 3];
                const float v = (s[0] - T[0]) * R[0 * 3 + rr]
                              + (s[1] - T[1]) * R[1 * 3 + rr]
                              + (s[2] - T[2]) * R[2 * 3 + rr];
                sro[(h * 2 + r) * 12 + u] = v;
                g_results[(size_t)i * 1920 + 192 + (h * 4 + p) * 3 + rr] = v;
            }
            __syncwarp();
            if (lane < 8) {
                const int r = lane / 4, p = lane % 4, i = i0 + r;
                const float* s = &sro[(h * 2 + r) * 12 + p * 3];
                g_results[(size_t)i * 1920 + 336 + h * 4 + p] =
                    sqrtf(s[0] * s[0] + s[1] * s[1] + s[2] * s[2] + EPSF);
            }
        }
    }
}

// ============ kernel 2b: combine r_pair j-slice partials ============
__global__ void __launch_bounds__(384) k_comb() {
    const int i = blockIdx.x, t = threadIdx.x;
    const float4 a = *reinterpret_cast<const float4*>(&g_rp[0][(size_t)i * 1536 + t * 4]);
    const float4 b = *reinterpret_cast<const float4*>(&g_rp[1][(size_t)i * 1536 + t * 4]);
    const float4 c = *reinterpret_cast<const float4*>(&g_rp[2][(size_t)i * 1536 + t * 4]);
    *reinterpret_cast<float4*>(&g_results[(size_t)i * 1920 + 384 + t * 4]) =
        make_float4(a.x + b.x + c.x, a.y + b.y + c.y,
                    a.z + b.z + c.z, a.w + b.w + c.w);
}

// ============ kernel 3: output GEMM partials (grid 48 x 6); packed-row LDS.128 ============
__global__ void __launch_bounds__(384) k_out(const float* __restrict__ Wo) {
    __shared__ unsigned long long su[512];     // [cc(64)][q(8)] packed row-pairs
    const int i0 = blockIdx.x * 16, cbase = blockIdx.y * 320, o = threadIdx.x;
    unsigned long long acc[8];
#pragma unroll
    for (int q = 0; q < 8; q++) acc[q] = 0ull;

    for (int c0 = cbase; c0 < cbase + 320; c0 += 64) {
        __syncthreads();
        for (int k = o; k < 512; k += 384) {
            const int cc = k >> 3, q = k & 7;
            unsigned long long v;
            PACK2(v, __float_as_uint(g_results[(size_t)(i0 + 2 * q) * 1920 + c0 + cc]),
                     __float_as_uint(g_results[(size_t)(i0 + 2 * q + 1) * 1920 + c0 + cc]));
            su[(cc << 3) + q] = v;
        }
        __syncthreads();
#pragma unroll 8
        for (int cc = 0; cc < 64; cc++) {
            const float wv = __ldg(&Wo[(size_t)(c0 + cc) * DIMX + o]);
            unsigned long long ww;
            PACK2(ww, __float_as_uint(wv), __float_as_uint(wv));
#pragma unroll
            for (int q2 = 0; q2 < 4; q2++) {
                const ulonglong2 s =
                    *reinterpret_cast<const ulonglong2*>(&su[(cc << 3) + (q2 << 1)]);
                FMA_F32X2(acc[2 * q2],     s.x, ww, acc[2 * q2]);
                FMA_F32X2(acc[2 * q2 + 1], s.y, ww, acc[2 * q2 + 1]);
            }
        }
    }
    float* op = g_opart[blockIdx.y];
#pragma unroll
    for (int q = 0; q < 8; q++) {
        unsigned lo, hi; UNPK2(lo, hi, acc[q]);
        op[(size_t)(i0 + 2 * q) * DIMX + o]     = __uint_as_float(lo);
        op[(size_t)(i0 + 2 * q + 1) * DIMX + o] = __uint_as_float(hi);
    }
}

// ============ kernel 4: reduce partials + bias ============
__global__ void k_out_red(const float* __restrict__ bo, float* __restrict__ out) {
    const int i = blockIdx.x, o = threadIdx.x;
    const size_t idx = (size_t)i * DIMX + o;
    out[idx] = g_opart[0][idx] + g_opart[1][idx] + g_opart[2][idx]
             + g_opart[3][idx] + g_opart[4][idx] + g_opart[5][idx] + bo[o];
}

// ============ launch ============
extern "C" void kernel_launch(void* const* d_in, const int* in_sizes, int n_in,
                              void* d_out, int out_size) {
    const float* x    = (const float*)d_in[0];
    const float* pair = (const float*)d_in[1];
    const float* rot  = (const float*)d_in[2];
    const float* trs  = (const float*)d_in[3];
    // d_in[4] = mask (all true) -> no-op
    const float* Wq_s = (const float*)d_in[5];
    const float* Wk_s = (const float*)d_in[6];
    const float* Wv_s = (const float*)d_in[7];
    const float* Wq_p = (const float*)d_in[8];
    const float* Wk_p = (const float*)d_in[9];
    const float* Wv_p = (const float*)d_in[10];
    const float* Wpr  = (const float*)d_in[11];
    const float* bpr  = (const float*)d_in[12];
    const float* pwts = (const float*)d_in[13];
    const float* Wout = (const float*)d_in[14];
    const float* bout = (const float*)d_in[15];
    float* out = (float*)d_out;

    static bool attr_done = false;
    if (!attr_done) {
        cudaFuncSetAttribute(k_fused, cudaFuncAttributeMaxDynamicSharedMemorySize, 84912);
        attr_done = true;
    }

    k_proj<<<NN / 8, 1008>>>(x, Wq_s, Wk_s, Wv_s, Wq_p, Wk_p, Wv_p, rot, trs);
    k_fused<<<NN / 2, 512, 84912>>>(pair, Wpr, bpr, rot, trs, pwts);
    k_comb<<<NN, 384>>>();
    k_out<<<dim3(NN / 16, 6), 384>>>(Wout);
    k_out_red<<<NN, DIMX>>>(bout, out);
}

// round 16
// speedup vs baseline: 1.5162x; 1.2955x over previous
#include <cuda_runtime.h>
#include <cuda_bf16.h>
#include <math.h>
#include <float.h>

#define NN   768
#define DIMX 384
#define HH   12
#define PDD  128

static __device__ __constant__ float SCALAR_SCALE = 0.14433756729740643f; // (3*16)^-0.5
static __device__ __constant__ float POINT_SCALE  = 0.13608276348795434f; // (3*4*4.5)^-0.5
static __device__ __constant__ float PAIR_SCALE   = 0.5773502691896258f;  // 3^-0.5
#define EPSF 1e-8f

// ---- packed f32x2 helpers (sm_103a) ----
#define FMA_F32X2(d, a, b, c) \
    asm("fma.rn.f32x2 %0, %1, %2, %3;" : "=l"(d) : "l"(a), "l"(b), "l"(c))
#define PACK2(out, lo_u, hi_u) \
    asm("mov.b64 %0, {%1, %2};" : "=l"(out) : "r"(lo_u), "r"(hi_u))
#define UNPK2(lo_u, hi_u, in) \
    asm("mov.b64 {%0, %1}, %2;" : "=r"(lo_u), "=r"(hi_u) : "l"(in))

// ---- scratch ----
__device__ float g_qs[HH * NN * 16];
__device__ float g_qp[HH * NN * 12];
__device__ float g_kT[HH * 28 * NN];           // transposed k-features: [h][d(28)][j]
__device__ float g_vT[HH * 28 * NN];           // transposed v-features: [h][d(28)][j]
__device__ float g_results[(size_t)NN * 1920];
__device__ float g_opart[6][(size_t)NN * DIMX];

// ============ kernel 1: all projections, 8 residues/block, f32x2 row pairs ============
__global__ void __launch_bounds__(1008)
k_proj(const float* __restrict__ x,
       const float* __restrict__ Wqs, const float* __restrict__ Wks,
       const float* __restrict__ Wvs,
       const float* __restrict__ Wqp, const float* __restrict__ Wkp,
       const float* __restrict__ Wvp,
       const float* __restrict__ rot, const float* __restrict__ trs) {
    __shared__ unsigned long long spack[DIMX][4];
    __shared__ float sloc[8][432];
    const int i0 = blockIdx.x * 8, t = threadIdx.x;

    for (int k = t; k < 4 * DIMX; k += 1008) {
        const int rp = k / DIMX, c = k % DIMX;
        unsigned long long v;
        PACK2(v, __float_as_uint(x[(i0 + 2 * rp) * DIMX + c]),
                 __float_as_uint(x[(i0 + 2 * rp + 1) * DIMX + c]));
        spack[c][rp] = v;
    }
    __syncthreads();

    unsigned long long acc[4] = {0ull, 0ull, 0ull, 0ull};
    if (t < 576) {
        const float* W; int cc;
        if (t < 192)      { W = Wqs; cc = t; }
        else if (t < 384) { W = Wks; cc = t - 192; }
        else              { W = Wvs; cc = t - 384; }
#pragma unroll 4
        for (int c = 0; c < DIMX; c++) {
            const float w = __ldg(&W[c * 192 + cc]);
            unsigned long long wp; PACK2(wp, __float_as_uint(w), __float_as_uint(w));
#pragma unroll
            for (int q = 0; q < 4; q++) FMA_F32X2(acc[q], spack[c][q], wp, acc[q]);
        }
        const int h = (t % 192) >> 4, d = t & 15;
#pragma unroll
        for (int q = 0; q < 4; q++) {
            unsigned lo, hi; UNPK2(lo, hi, acc[q]);
            if (t < 192) {
                g_qs[((h * NN) + i0 + 2 * q) * 16 + d]     = __uint_as_float(lo);
                g_qs[((h * NN) + i0 + 2 * q + 1) * 16 + d] = __uint_as_float(hi);
            } else if (t < 384) {
                g_kT[(h * 28 + d) * NN + i0 + 2 * q]     = __uint_as_float(lo);
                g_kT[(h * 28 + d) * NN + i0 + 2 * q + 1] = __uint_as_float(hi);
            } else {
                g_vT[(h * 28 + d) * NN + i0 + 2 * q]     = __uint_as_float(lo);
                g_vT[(h * 28 + d) * NN + i0 + 2 * q + 1] = __uint_as_float(hi);
            }
        }
    } else {
        const int cc = t - 576, m = cc / 144, ccl = cc % 144;
        const float* W = (m == 0) ? Wqp : (m == 1) ? Wkp : Wvp;
#pragma unroll 4
        for (int c = 0; c < DIMX; c++) {
            const float w = __ldg(&W[c * 144 + ccl]);
            unsigned long long wp; PACK2(wp, __float_as_uint(w), __float_as_uint(w));
#pragma unroll
            for (int q = 0; q < 4; q++) FMA_F32X2(acc[q], spack[c][q], wp, acc[q]);
        }
#pragma unroll
        for (int q = 0; q < 4; q++) {
            unsigned lo, hi; UNPK2(lo, hi, acc[q]);
            sloc[2 * q][cc]     = __uint_as_float(lo);
            sloc[2 * q + 1][cc] = __uint_as_float(hi);
        }
    }
    __syncthreads();
    if (t >= 576) {
        const int cc = t - 576, m = cc / 144, ccl = cc % 144;
        const int rr = ccl % 3, hp = ccl / 3, h = hp >> 2, p = hp & 3;
        const int base = m * 144 + hp * 3;
#pragma unroll
        for (int r = 0; r < 8; r++) {
            const float* R = rot + (i0 + r) * 9;
            const float v = sloc[r][base + 0] * R[rr * 3 + 0]
                          + sloc[r][base + 1] * R[rr * 3 + 1]
                          + sloc[r][base + 2] * R[rr * 3 + 2]
                          + trs[(i0 + r) * 3 + rr];
            if (m == 0)      g_qp[((h * NN) + i0 + r) * 12 + p * 3 + rr] = v;
            else if (m == 1) g_kT[(h * 28 + 16 + p * 3 + rr) * NN + i0 + r] = v;
            else             g_vT[(h * 28 + 16 + p * 3 + rr) * NN + i0 + r] = v;
        }
    }
}

// ============ kernel 2: fused qk + bias + softmax + r_pair + r_scalar/point ============
// 768 threads = 24 warps; 2 query residues per block; 1 block/SM (158KB smem).
// smem float layout:
//   sl    [0, 18432)         24 rows x 768 logits/attn
//   sacc  [18432, 36864)     phase-3 partials [2r][6 slices][12 h][128 d]
//   sW    [36864, 38400)     W_pair^T as f4: [12 h][32 d4]
//   sq    [38400, 39072)     24 rows x 28 q-features
//   sbp   [39072, 39084)     b_pair
//   sp2   [39084, 39372)     [h][r][12]
//   sro   [39372, 39660)     [h][r][12]
__global__ void __launch_bounds__(768)
k_fused(const float* __restrict__ pair, const float* __restrict__ Wp,
        const float* __restrict__ bp,
        const float* __restrict__ rot, const float* __restrict__ trs,
        const float* __restrict__ pwts) {
    extern __shared__ float sdyn[];
    float* sl   = sdyn;
    float* sacc = sdyn + 18432;
    float* sW   = sdyn + 36864;
    float* sq   = sdyn + 38400;
    float* sbp  = sdyn + 39072;
    float* sp2  = sdyn + 39084;
    float* sro  = sdyn + 39372;
    const int i0 = blockIdx.x * 2, t = threadIdx.x, w = t >> 5, lane = t & 31;

    // ---- stage W_pair^T f4, q features, b_pair ----
    if (t < 384) {
        const int h = t >> 5, d4 = t & 31;
        const float4 v = make_float4(__ldg(&Wp[(d4 * 4 + 0) * HH + h]),
                                     __ldg(&Wp[(d4 * 4 + 1) * HH + h]),
                                     __ldg(&Wp[(d4 * 4 + 2) * HH + h]),
                                     __ldg(&Wp[(d4 * 4 + 3) * HH + h]));
        *reinterpret_cast<float4*>(&sW[(h * 32 + d4) * 4]) = v;
    }
    if (t < 672) {
        const int row = t / 28, dd = t % 28, r = row / 12, h = row % 12;
        sq[row * 28 + dd] = (dd < 16) ? g_qs[(h * NN + i0 + r) * 16 + dd]
                                      : g_qp[(h * NN + i0 + r) * 12 + dd - 16];
    }
    if (t < 12) sbp[t] = __ldg(&bp[t]);
    __syncthreads();

    // ---- phase 0: qk logits via transposed k (coalesced LDG.32) ----
    {
        const int row = w, h = w % 12;
        const float coef = 0.5f * POINT_SCALE * log1pf(expf(__ldg(&pwts[h])));
        const float* kT = g_kT + (size_t)h * 28 * NN;
        const float* sqr = sq + row * 28;
        for (int j = lane; j < NN; j += 32) {
            float dot = 0.f, dist = 0.f;
#pragma unroll
            for (int d = 0; d < 16; d++) dot = fmaf(sqr[d], __ldg(&kT[d * NN + j]), dot);
#pragma unroll
            for (int d = 0; d < 12; d++) {
                const float df = sqr[16 + d] - __ldg(&kT[(16 + d) * NN + j]);
                dist = fmaf(df, df, dist);
            }
            sl[row * NN + j] = fmaf(dot, SCALAR_SCALE, -coef * dist);
        }
    }
    __syncthreads();

    // ---- phase 1: pair-bias GEMM; 8 j-rows x 4 d-lanes per warp group (nL=8) ----
    {
        const int jr = lane >> 2, dd = lane & 3;
#pragma unroll
        for (int gi = 0; gi < 8; gi++) {
            const int g = w + gi * 24;            // 0..191
            const int r = g / 96, jb = (g % 96) * 8 + jr;
            const ulonglong2* prow = reinterpret_cast<const ulonglong2*>(
                pair + ((size_t)(i0 + r) * NN + jb) * PDD);
            unsigned long long acc[12];
#pragma unroll
            for (int h = 0; h < 12; h++) acc[h] = 0ull;
#pragma unroll
            for (int q = 0; q < 8; q++) {
                const ulonglong2 p = __ldg(&prow[q * 4 + dd]);
#pragma unroll
                for (int h = 0; h < 12; h++) {
                    const ulonglong2 wv = *reinterpret_cast<const ulonglong2*>(
                        &sW[(h * 32 + q * 4 + dd) * 4]);
                    FMA_F32X2(acc[h], p.x, wv.x, acc[h]);
                    FMA_F32X2(acc[h], p.y, wv.y, acc[h]);
                }
            }
            float b[12];
#pragma unroll
            for (int h = 0; h < 12; h++) {
                unsigned lo, hi; UNPK2(lo, hi, acc[h]);
                b[h] = __uint_as_float(lo) + __uint_as_float(hi);
                b[h] += __shfl_xor_sync(0xffffffffu, b[h], 1);
                b[h] += __shfl_xor_sync(0xffffffffu, b[h], 2);
            }
#pragma unroll
            for (int u = 0; u < 3; u++) {
                const int h = dd * 3 + u;
                float* p = &sl[(r * 12 + h) * NN + jb];
                *p = fmaf(b[h] + sbp[h], PAIR_SCALE, *p);
            }
        }
    }
    __syncthreads();

    // ---- phase 2: softmax per row (24 rows = 24 warps) ----
    {
        float* rl = sl + w * NN;
        float m = -FLT_MAX;
        for (int j = lane; j < NN; j += 32) m = fmaxf(m, rl[j]);
#pragma unroll
        for (int off = 16; off; off >>= 1) m = fmaxf(m, __shfl_xor_sync(0xffffffffu, m, off));
        float s = 0.f;
        for (int j = lane; j < NN; j += 32) { const float e = __expf(rl[j] - m); rl[j] = e; s += e; }
#pragma unroll
        for (int off = 16; off; off >>= 1) s += __shfl_xor_sync(0xffffffffu, s, off);
        const float inv = 1.f / s;
        for (int j = lane; j < NN; j += 32) rl[j] *= inv;
    }
    __syncthreads();

    // ---- phase 3: split roles: 12 pair-warps (all h per read) + 12 v-warps ----
    if (w < 12) {
        const int r = w & 1, slice = w >> 1, j0 = slice * 128;
        unsigned long long acc[12][2];
#pragma unroll
        for (int h = 0; h < 12; h++) { acc[h][0] = 0ull; acc[h][1] = 0ull; }
        const float4* pbase = reinterpret_cast<const float4*>(
            pair + (size_t)(i0 + r) * NN * PDD) + lane;
        const float* arow = sl + r * 12 * NN + j0;
#pragma unroll 2
        for (int j = 0; j < 128; j++) {
            const float4 p = __ldg(pbase + (size_t)(j0 + j) * 32);
            unsigned long long p01, p23;
            PACK2(p01, __float_as_uint(p.x), __float_as_uint(p.y));
            PACK2(p23, __float_as_uint(p.z), __float_as_uint(p.w));
#pragma unroll
            for (int h = 0; h < 12; h++) {
                const float a = arow[h * NN + j];
                unsigned long long aa;
                PACK2(aa, __float_as_uint(a), __float_as_uint(a));
                FMA_F32X2(acc[h][0], p01, aa, acc[h][0]);
                FMA_F32X2(acc[h][1], p23, aa, acc[h][1]);
            }
        }
#pragma unroll
        for (int h = 0; h < 12; h++) {
            unsigned a0, a1, b0, b1;
            UNPK2(a0, a1, acc[h][0]); UNPK2(b0, b1, acc[h][1]);
            *reinterpret_cast<float4*>(&sacc[((r * 6 + slice) * 12 + h) * 128 + lane * 4]) =
                make_float4(__uint_as_float(a0), __uint_as_float(a1),
                            __uint_as_float(b0), __uint_as_float(b1));
        }
    } else {
        // ---- v-warps: warp = head; loop over 28 features, contiguous-j loads (nL=1) ----
        const int h = w - 12;
        const float* s0 = sl + h * NN;
        const float* s1 = sl + (12 + h) * NN;
        for (int d = 0; d < 28; d++) {
            const float* vrow = g_vT + (size_t)(h * 28 + d) * NN;
            float a0 = 0.f, a1 = 0.f;
#pragma unroll 4
            for (int jc = 0; jc < 24; jc++) {
                const int j = jc * 32 + lane;
                const float v = __ldg(&vrow[j]);
                a0 = fmaf(s0[j], v, a0);
                a1 = fmaf(s1[j], v, a1);
            }
#pragma unroll
            for (int off = 16; off; off >>= 1) {
                a0 += __shfl_xor_sync(0xffffffffu, a0, off);
                a1 += __shfl_xor_sync(0xffffffffu, a1, off);
            }
            if (lane == 0) {
                if (d < 16) {
                    g_results[(size_t)(i0 + 0) * 1920 + h * 16 + d] = a0;
                    g_results[(size_t)(i0 + 1) * 1920 + h * 16 + d] = a1;
                } else {
                    sp2[(h * 2 + 0) * 12 + d - 16] = a0;
                    sp2[(h * 2 + 1) * 12 + d - 16] = a1;
                }
            }
        }
        __syncwarp();
        if (lane < 24) {
            const int r = lane / 12, u = lane % 12, p = u / 3, rr = u % 3;
            const int i = i0 + r;
            const float* R = rot + i * 9;
            const float* T = trs + i * 3;
            const float* s = &sp2[(h * 2 + r) * 12 + p * 3];
            const float v = (s[0] - T[0]) * R[0 * 3 + rr]
                          + (s[1] - T[1]) * R[1 * 3 + rr]
                          + (s[2] - T[2]) * R[2 * 3 + rr];
            sro[(h * 2 + r) * 12 + u] = v;
            g_results[(size_t)i * 1920 + 192 + (h * 4 + p) * 3 + rr] = v;
        }
        __syncwarp();
        if (lane < 8) {
            const int r = lane / 4, p = lane % 4, i = i0 + r;
            const float* s = &sro[(h * 2 + r) * 12 + p * 3];
            g_results[(size_t)i * 1920 + 336 + h * 4 + p] =
                sqrtf(s[0] * s[0] + s[1] * s[1] + s[2] * s[2] + EPSF);
        }
    }
    __syncthreads();

    // ---- reduce pair-slice partials -> g_results ----
    for (int idx = t; idx < 3072; idx += 768) {
        const int r = idx / 1536, rem = idx % 1536, h = rem / 128, d = rem % 128;
        float v = 0.f;
#pragma unroll
        for (int s = 0; s < 6; s++) v += sacc[((r * 6 + s) * 12 + h) * 128 + d];
        g_results[(size_t)(i0 + r) * 1920 + 384 + h * 128 + d] = v;
    }
}

// ============ kernel 3: output GEMM partials (grid 48 x 6); packed-row LDS.128 ============
__global__ void __launch_bounds__(384) k_out(const float* __restrict__ Wo) {
    __shared__ unsigned long long su[512];     // [cc(64)][q(8)] packed row-pairs
    const int i0 = blockIdx.x * 16, cbase = blockIdx.y * 320, o = threadIdx.x;
    unsigned long long acc[8];
#pragma unroll
    for (int q = 0; q < 8; q++) acc[q] = 0ull;

    for (int c0 = cbase; c0 < cbase + 320; c0 += 64) {
        __syncthreads();
        for (int k = o; k < 512; k += 384) {
            const int cc = k >> 3, q = k & 7;
            unsigned long long v;
            PACK2(v, __float_as_uint(g_results[(size_t)(i0 + 2 * q) * 1920 + c0 + cc]),
                     __float_as_uint(g_results[(size_t)(i0 + 2 * q + 1) * 1920 + c0 + cc]));
            su[(cc << 3) + q] = v;
        }
        __syncthreads();
#pragma unroll 8
        for (int cc = 0; cc < 64; cc++) {
            const float wv = __ldg(&Wo[(size_t)(c0 + cc) * DIMX + o]);
            unsigned long long ww;
            PACK2(ww, __float_as_uint(wv), __float_as_uint(wv));
#pragma unroll
            for (int q2 = 0; q2 < 4; q2++) {
                const ulonglong2 s =
                    *reinterpret_cast<const ulonglong2*>(&su[(cc << 3) + (q2 << 1)]);
                FMA_F32X2(acc[2 * q2],     s.x, ww, acc[2 * q2]);
                FMA_F32X2(acc[2 * q2 + 1], s.y, ww, acc[2 * q2 + 1]);
            }
        }
    }
    float* op = g_opart[blockIdx.y];
#pragma unroll
    for (int q = 0; q < 8; q++) {
        unsigned lo, hi; UNPK2(lo, hi, acc[q]);
        op[(size_t)(i0 + 2 * q) * DIMX + o]     = __uint_as_float(lo);
        op[(size_t)(i0 + 2 * q + 1) * DIMX + o] = __uint_as_float(hi);
    }
}

// ============ kernel 4: reduce partials + bias ============
__global__ void k_out_red(const float* __restrict__ bo, float* __restrict__ out) {
    const int i = blockIdx.x, o = threadIdx.x;
    const size_t idx = (size_t)i * DIMX + o;
    out[idx] = g_opart[0][idx] + g_opart[1][idx] + g_opart[2][idx]
             + g_opart[3][idx] + g_opart[4][idx] + g_opart[5][idx] + bo[o];
}

// ============ launch ============
extern "C" void kernel_launch(void* const* d_in, const int* in_sizes, int n_in,
                              void* d_out, int out_size) {
    const float* x    = (const float*)d_in[0];
    const float* pair = (const float*)d_in[1];
    const float* rot  = (const float*)d_in[2];
    const float* trs  = (const float*)d_in[3];
    // d_in[4] = mask (all true) -> no-op
    const float* Wq_s = (const float*)d_in[5];
    const float* Wk_s = (const float*)d_in[6];
    const float* Wv_s = (const float*)d_in[7];
    const float* Wq_p = (const float*)d_in[8];
    const float* Wk_p = (const float*)d_in[9];
    const float* Wv_p = (const float*)d_in[10];
    const float* Wpr  = (const float*)d_in[11];
    const float* bpr  = (const float*)d_in[12];
    const float* pwts = (const float*)d_in[13];
    const float* Wout = (const float*)d_in[14];
    const float* bout = (const float*)d_in[15];
    float* out = (float*)d_out;

    static bool attr_done = false;
    if (!attr_done) {
        cudaFuncSetAttribute(k_fused, cudaFuncAttributeMaxDynamicSharedMemorySize, 158640);
        attr_done = true;
    }

    k_proj<<<NN / 8, 1008>>>(x, Wq_s, Wk_s, Wv_s, Wq_p, Wk_p, Wv_p, rot, trs);
    k_fused<<<NN / 2, 768, 158640>>>(pair, Wpr, bpr, rot, trs, pwts);
    k_out<<<dim3(NN / 16, 6), 384>>>(Wout);
    k_out_red<<<NN, DIMX>>>(bout, out);
}